// round 6
// baseline (speedup 1.0000x reference)
#include <cuda_runtime.h>
#include <cuda_bf16.h>
#include <mma.h>
#include <cstdint>
#include <cstddef>

using namespace nvcuda;

// Problem constants
constexpr int Bq = 8;
constexpr int T  = 200;
constexpr int U  = 50;
constexpr int D  = 512;    // K
constexpr int V  = 1024;   // N
constexpr int M_ENC  = Bq * T;    // 1600
constexpr int M_PRED = Bq * U;    // 400
constexpr int MP_PAD = 448;       // pred rows padded to 7*64

// Tiling (R2-proven: KC=16, depth-2 cp.async)
constexpr int BM  = 64;
constexpr int BN  = 128;
constexpr int KC  = 16;
constexpr int NS  = D / KC;      // 32 stages
constexpr int PAD = 4;
constexpr int LDS_ = KC + PAD;   // 20 floats

// Epilogue smem tile: 64 x 128 with pad
constexpr int ELD = BN + 4;      // 132 floats (16B-multiple)

// Scratch: Ppb rows = pred @ W^T  (bias added later in fused epilogue)
__device__ float Ppb[MP_PAD * V];

__device__ __forceinline__ void cp_async16(float* smem_dst, const float* gsrc, int src_bytes) {
    uint32_t s = (uint32_t)__cvta_generic_to_shared(smem_dst);
    asm volatile("cp.async.cg.shared.global [%0], [%1], 16, %2;\n"
                 :: "r"(s), "l"(gsrc), "r"(src_bytes));
}
__device__ __forceinline__ void cp_commit() {
    asm volatile("cp.async.commit_group;\n" ::);
}

// ---------------------------------------------------------------------------
// Kernel 1: Ppb = pred @ W^T   (tf32 wmma, double-buffered cp.async)
// ---------------------------------------------------------------------------
__global__ __launch_bounds__(256)
void pred_gemm_kernel(const float* __restrict__ pred,
                      const float* __restrict__ W)
{
    __shared__ float As[2][BM * LDS_];
    __shared__ float Bs[2][BN * LDS_];

    const int m0 = blockIdx.y * BM;
    const int n0 = blockIdx.x * BN;
    const int tid  = threadIdx.x;
    const int warp = tid >> 5;           // 8 warps: 2(M) x 4(N)
    const int wm   = (warp >> 2) * 32;   // 0 / 32
    const int wn   = (warp & 3)  * 32;   // 0..96

    wmma::fragment<wmma::accumulator, 16, 16, 8, float> acc[2][2];
#pragma unroll
    for (int i = 0; i < 2; i++)
#pragma unroll
        for (int j = 0; j < 2; j++)
            wmma::fill_fragment(acc[i][j], 0.0f);

    auto load_stage = [&](int ks, int buf) {
        const int k0 = ks * KC;
        // A: 64 rows x 16 floats = 256 chunks, 1/thread
        {
            const int r  = tid >> 2;
            const int c  = (tid & 3) * 4;
            const int gr = m0 + r;
            const float* src = pred + (size_t)gr * D + k0 + c;
            cp_async16(&As[buf][r * LDS_ + c], src, gr < M_PRED ? 16 : 0);
        }
        // B: 128 rows x 16 floats = 512 chunks, 2/thread
#pragma unroll
        for (int t = 0; t < 2; t++) {
            const int idx = tid + t * 256;
            const int n   = idx >> 2;
            const int c   = (idx & 3) * 4;
            cp_async16(&Bs[buf][n * LDS_ + c], W + (size_t)(n0 + n) * D + k0 + c, 16);
        }
        cp_commit();
    };

    load_stage(0, 0);

    for (int ks = 0; ks < NS; ks++) {
        const int buf = ks & 1;
        if (ks + 1 < NS) {
            load_stage(ks + 1, buf ^ 1);
            asm volatile("cp.async.wait_group 1;\n" ::);
        } else {
            asm volatile("cp.async.wait_group 0;\n" ::);
        }
        __syncthreads();

#pragma unroll
        for (int kk = 0; kk < KC; kk += 8) {
            wmma::fragment<wmma::matrix_a, 16, 16, 8, wmma::precision::tf32, wmma::row_major> af[2];
            wmma::fragment<wmma::matrix_b, 16, 16, 8, wmma::precision::tf32, wmma::col_major> bf[2];
#pragma unroll
            for (int i = 0; i < 2; i++) {
                wmma::load_matrix_sync(af[i], &As[buf][(wm + i * 16) * LDS_ + kk], LDS_);
#pragma unroll
                for (int t = 0; t < af[i].num_elements; t++)
                    af[i].x[t] = wmma::__float_to_tf32(af[i].x[t]);
            }
#pragma unroll
            for (int j = 0; j < 2; j++) {
                wmma::load_matrix_sync(bf[j], &Bs[buf][(wn + j * 16) * LDS_ + kk], LDS_);
#pragma unroll
                for (int t = 0; t < bf[j].num_elements; t++)
                    bf[j].x[t] = wmma::__float_to_tf32(bf[j].x[t]);
            }
#pragma unroll
            for (int i = 0; i < 2; i++)
#pragma unroll
                for (int j = 0; j < 2; j++)
                    wmma::mma_sync(acc[i][j], af[i], bf[j], acc[i][j]);
        }
        __syncthreads();
    }

#pragma unroll
    for (int i = 0; i < 2; i++)
#pragma unroll
        for (int j = 0; j < 2; j++)
            wmma::store_matrix_sync(&Ppb[(size_t)(m0 + wm + i * 16) * V + (n0 + wn + j * 16)],
                                    acc[i][j], V, wmma::mem_row_major);
}

// ---------------------------------------------------------------------------
// Kernel 2 (fused): E-tile GEMM -> smem -> broadcast epilogue
//   out[bt,u,n0:n0+128] = E[bt,n0:] + bias[n0:] + Ppb[b*U+u, n0:]
//   200 CTAs all co-resident (2/SM): one CTA's MMA overlaps the other's
//   store flood on the same SM.
// ---------------------------------------------------------------------------
__global__ __launch_bounds__(256, 2)
void joiner_fused_kernel(const float* __restrict__ enc,
                         const float* __restrict__ W,
                         const float* __restrict__ bias,
                         float* __restrict__ out)
{
    extern __shared__ float dsm[];
    // K-loop layout (30720 B) and E-tile layout (33792 B) alias in dsm.
    float* As0 = dsm;                         // [2][BM*LDS_] = 2*1280
    float* Bs0 = dsm + 2 * BM * LDS_;         // [2][BN*LDS_] = 2*2560
    float* Es  = dsm;                         // [BM][ELD]    = 8448

    const int m0 = blockIdx.y * BM;           // 25 tiles, exact (1600/64)
    const int n0 = blockIdx.x * BN;
    const int tid  = threadIdx.x;
    const int warp = tid >> 5;
    const int wm   = (warp >> 2) * 32;
    const int wn   = (warp & 3)  * 32;

    wmma::fragment<wmma::accumulator, 16, 16, 8, float> acc[2][2];
#pragma unroll
    for (int i = 0; i < 2; i++)
#pragma unroll
        for (int j = 0; j < 2; j++)
            wmma::fill_fragment(acc[i][j], 0.0f);

    auto load_stage = [&](int ks, int buf) {
        const int k0 = ks * KC;
        {
            const int r = tid >> 2;
            const int c = (tid & 3) * 4;
            cp_async16(&As0[buf * BM * LDS_ + r * LDS_ + c],
                       enc + (size_t)(m0 + r) * D + k0 + c, 16);
        }
#pragma unroll
        for (int t = 0; t < 2; t++) {
            const int idx = tid + t * 256;
            const int n   = idx >> 2;
            const int c   = (idx & 3) * 4;
            cp_async16(&Bs0[buf * BN * LDS_ + n * LDS_ + c],
                       W + (size_t)(n0 + n) * D + k0 + c, 16);
        }
        cp_commit();
    };

    load_stage(0, 0);

    for (int ks = 0; ks < NS; ks++) {
        const int buf = ks & 1;
        if (ks + 1 < NS) {
            load_stage(ks + 1, buf ^ 1);
            asm volatile("cp.async.wait_group 1;\n" ::);
        } else {
            asm volatile("cp.async.wait_group 0;\n" ::);
        }
        __syncthreads();

#pragma unroll
        for (int kk = 0; kk < KC; kk += 8) {
            wmma::fragment<wmma::matrix_a, 16, 16, 8, wmma::precision::tf32, wmma::row_major> af[2];
            wmma::fragment<wmma::matrix_b, 16, 16, 8, wmma::precision::tf32, wmma::col_major> bf[2];
#pragma unroll
            for (int i = 0; i < 2; i++) {
                wmma::load_matrix_sync(af[i], &As0[buf * BM * LDS_ + (wm + i * 16) * LDS_ + kk], LDS_);
#pragma unroll
                for (int t = 0; t < af[i].num_elements; t++)
                    af[i].x[t] = wmma::__float_to_tf32(af[i].x[t]);
            }
#pragma unroll
            for (int j = 0; j < 2; j++) {
                wmma::load_matrix_sync(bf[j], &Bs0[buf * BN * LDS_ + (wn + j * 16) * LDS_ + kk], LDS_);
#pragma unroll
                for (int t = 0; t < bf[j].num_elements; t++)
                    bf[j].x[t] = wmma::__float_to_tf32(bf[j].x[t]);
            }
#pragma unroll
            for (int i = 0; i < 2; i++)
#pragma unroll
                for (int j = 0; j < 2; j++)
                    wmma::mma_sync(acc[i][j], af[i], bf[j], acc[i][j]);
        }
        __syncthreads();
    }

    // Park E tile in smem (acc regs -> Es), then broadcast epilogue.
#pragma unroll
    for (int i = 0; i < 2; i++)
#pragma unroll
        for (int j = 0; j < 2; j++)
            wmma::store_matrix_sync(&Es[(wm + i * 16) * ELD + (wn + j * 16)],
                                    acc[i][j], ELD, wmma::mem_row_major);
    __syncthreads();

    // Epilogue: warp w handles rows [w*8, w*8+8); lanes cover 128 cols as float4.
    const int c4 = (tid & 31) * 4;           // col offset 0..124
    const int rg = warp * 8;                 // row group base

    float4 bb = *reinterpret_cast<const float4*>(bias + n0 + c4);

#pragma unroll
    for (int i = 0; i < 8; i++) {
        const int row = rg + i;
        const int bt  = m0 + row;
        const int b   = bt / T;

        float4 e = *reinterpret_cast<const float4*>(&Es[row * ELD + c4]);
        e.x += bb.x; e.y += bb.y; e.z += bb.z; e.w += bb.w;

        const float* Pb = Ppb + (size_t)(b * U) * V + n0 + c4;
        float*       Ob = out + ((size_t)bt * U) * V + n0 + c4;

#pragma unroll 5
        for (int u = 0; u < U; u++) {
            float4 p = *reinterpret_cast<const float4*>(Pb + (size_t)u * V);
            float4 o;
            o.x = e.x + p.x;
            o.y = e.y + p.y;
            o.z = e.z + p.z;
            o.w = e.w + p.w;
            *reinterpret_cast<float4*>(Ob + (size_t)u * V) = o;
        }
    }
}

// ---------------------------------------------------------------------------
extern "C" void kernel_launch(void* const* d_in, const int* in_sizes, int n_in,
                              void* d_out, int out_size)
{
    const float* enc  = (const float*)d_in[0];   // [B,T,D]
    const float* pred = (const float*)d_in[1];   // [B,U,D]
    const float* W    = (const float*)d_in[2];   // [V,D]
    const float* bias = (const float*)d_in[3];   // [V]
    float* out = (float*)d_out;                  // [B,T,U,V]

    // Kernel 1: P = pred @ W^T  (448-padded rows, 7x8 = 56 CTAs)
    dim3 pgrid(V / BN, MP_PAD / BM);
    pred_gemm_kernel<<<pgrid, 256>>>(pred, W);

    // Kernel 2: fused E-GEMM + broadcast (25x8 = 200 CTAs, all resident)
    constexpr int DSM = (BM * ELD) * 4 > (2 * (BM + BN) * LDS_) * 4
                      ? (BM * ELD) * 4 : (2 * (BM + BN) * LDS_) * 4;   // 33792
    dim3 fgrid(V / BN, M_ENC / BM);
    joiner_fused_kernel<<<fgrid, 256, DSM>>>(enc, W, bias, out);
}

// round 7
// speedup vs baseline: 1.7515x; 1.7515x over previous
#include <cuda_runtime.h>
#include <cuda_bf16.h>
#include <mma.h>
#include <cstdint>
#include <cstddef>

using namespace nvcuda;

// Problem constants
constexpr int Bq = 8;
constexpr int T  = 200;
constexpr int U  = 50;
constexpr int D  = 512;    // K
constexpr int V  = 1024;   // N
constexpr int M_ENC  = Bq * T;          // 1600
constexpr int M_TOT  = M_ENC + Bq * U;  // 2000
constexpr int M_PAD  = 2048;

// GEMM tiling: BM=64 for 256 CTAs (~1.7/SM) and 2 CTAs/SM residency
constexpr int BM  = 64;
constexpr int BN  = 128;
constexpr int KC  = 16;          // k-chunk per stage (proven depth-2 config)
constexpr int NS  = D / KC;      // 32 stages
constexpr int PAD = 4;
constexpr int LDS_ = KC + PAD;   // 20 floats row stride

// Scratch: EP[m, v]  (rows 0..1599 = enc@W^T, rows 1600..1999 = pred@W^T)
__device__ float EP[M_PAD * V];

__device__ __forceinline__ void cp_async16(float* smem_dst, const float* gsrc, int src_bytes) {
    uint32_t s = (uint32_t)__cvta_generic_to_shared(smem_dst);
    asm volatile("cp.async.cg.shared.global [%0], [%1], 16, %2;\n"
                 :: "r"(s), "l"(gsrc), "r"(src_bytes));
}
__device__ __forceinline__ void cp_commit() {
    asm volatile("cp.async.commit_group;\n" ::);
}

// ---------------------------------------------------------------------------
// Kernel 1: EP = [enc; pred] @ W^T  (tf32 wmma, fp32 accum, double buffer)
//   64x128 tiles -> 256 CTAs, 2 CTAs/SM.
// ---------------------------------------------------------------------------
__global__ __launch_bounds__(256, 2)
void joiner_gemm_kernel(const float* __restrict__ enc,
                        const float* __restrict__ pred,
                        const float* __restrict__ W)
{
    __shared__ float As[2][BM * LDS_];   // (m, k) row-major, lda = LDS_
    __shared__ float Bs[2][BN * LDS_];   // (n, k) -> col_major view

    const int m0 = blockIdx.y * BM;
    const int n0 = blockIdx.x * BN;
    const int tid  = threadIdx.x;        // 256
    const int warp = tid >> 5;           // 8 warps: 2(M) x 4(N)
    const int wm   = (warp >> 2) * 32;   // 0 / 32
    const int wn   = (warp & 3)  * 32;   // 0..96

    wmma::fragment<wmma::accumulator, 16, 16, 8, float> acc[2][2];
#pragma unroll
    for (int i = 0; i < 2; i++)
#pragma unroll
        for (int j = 0; j < 2; j++)
            wmma::fill_fragment(acc[i][j], 0.0f);

    auto load_stage = [&](int ks, int buf) {
        const int k0 = ks * KC;
        // A: 64 rows x 16 floats = 256 x 16B chunks, 1/thread
        {
            const int r  = tid >> 2;
            const int c  = (tid & 3) * 4;
            const int gr = m0 + r;
            const float* src = enc;      // dummy for zero-fill rows
            int sz = 0;
            if (gr < M_ENC)      { src = enc  + (size_t)gr * D + k0 + c;           sz = 16; }
            else if (gr < M_TOT) { src = pred + (size_t)(gr - M_ENC) * D + k0 + c; sz = 16; }
            cp_async16(&As[buf][r * LDS_ + c], src, sz);
        }
        // B: 128 rows x 16 floats = 512 chunks, 2/thread
#pragma unroll
        for (int t = 0; t < 2; t++) {
            const int idx = tid + t * 256;
            const int n   = idx >> 2;
            const int c   = (idx & 3) * 4;
            cp_async16(&Bs[buf][n * LDS_ + c], W + (size_t)(n0 + n) * D + k0 + c, 16);
        }
        cp_commit();
    };

    load_stage(0, 0);

    for (int ks = 0; ks < NS; ks++) {
        const int buf = ks & 1;
        if (ks + 1 < NS) {
            load_stage(ks + 1, buf ^ 1);
            asm volatile("cp.async.wait_group 1;\n" ::);
        } else {
            asm volatile("cp.async.wait_group 0;\n" ::);
        }
        __syncthreads();

#pragma unroll
        for (int kk = 0; kk < KC; kk += 8) {
            wmma::fragment<wmma::matrix_a, 16, 16, 8, wmma::precision::tf32, wmma::row_major> af[2];
            wmma::fragment<wmma::matrix_b, 16, 16, 8, wmma::precision::tf32, wmma::col_major> bf[2];
#pragma unroll
            for (int i = 0; i < 2; i++) {
                wmma::load_matrix_sync(af[i], &As[buf][(wm + i * 16) * LDS_ + kk], LDS_);
#pragma unroll
                for (int t = 0; t < af[i].num_elements; t++)
                    af[i].x[t] = wmma::__float_to_tf32(af[i].x[t]);
            }
#pragma unroll
            for (int j = 0; j < 2; j++) {
                wmma::load_matrix_sync(bf[j], &Bs[buf][(wn + j * 16) * LDS_ + kk], LDS_);
#pragma unroll
                for (int t = 0; t < bf[j].num_elements; t++)
                    bf[j].x[t] = wmma::__float_to_tf32(bf[j].x[t]);
            }
#pragma unroll
            for (int i = 0; i < 2; i++)
#pragma unroll
                for (int j = 0; j < 2; j++)
                    wmma::mma_sync(acc[i][j], af[i], bf[j], acc[i][j]);
        }
        __syncthreads();
    }

    // store (padded EP rows absorb the M=2000 ragged tail)
#pragma unroll
    for (int i = 0; i < 2; i++)
#pragma unroll
        for (int j = 0; j < 2; j++)
            wmma::store_matrix_sync(&EP[(size_t)(m0 + wm + i * 16) * V + (n0 + wn + j * 16)],
                                    acc[i][j], V, wmma::mem_row_major);
}

// ---------------------------------------------------------------------------
// Kernel 2: out[b,t,u,v] = EP[b*T+t, v] + EP[1600 + b*U+u, v] + bias[v]
//   Proven config (R1/R4): one CTA per (b,t), plain STG.128, unroll 5.
// ---------------------------------------------------------------------------
__global__ __launch_bounds__(256, 8)
void joiner_bcast_kernel(const float* __restrict__ bias,
                         float* __restrict__ out)
{
    const int bt  = blockIdx.x;          // 0..1599
    const int b   = bt / T;
    const int tid = threadIdx.x;         // 256 threads * 4 floats = V

    float4 e  = *reinterpret_cast<const float4*>(EP + (size_t)bt * V + tid * 4);
    float4 bb = *reinterpret_cast<const float4*>(bias + tid * 4);
    e.x += bb.x; e.y += bb.y; e.z += bb.z; e.w += bb.w;

    const float* Pbase = EP + (size_t)(M_ENC + b * U) * V + tid * 4;
    float*       Obase = out + (size_t)bt * U * V + tid * 4;

#pragma unroll 5
    for (int u = 0; u < U; u++) {
        float4 p = *reinterpret_cast<const float4*>(Pbase + (size_t)u * V);
        float4 o;
        o.x = e.x + p.x;
        o.y = e.y + p.y;
        o.z = e.z + p.z;
        o.w = e.w + p.w;
        *reinterpret_cast<float4*>(Obase + (size_t)u * V) = o;
    }
}

// ---------------------------------------------------------------------------
extern "C" void kernel_launch(void* const* d_in, const int* in_sizes, int n_in,
                              void* d_out, int out_size)
{
    const float* enc  = (const float*)d_in[0];   // [B,T,D]
    const float* pred = (const float*)d_in[1];   // [B,U,D]
    const float* W    = (const float*)d_in[2];   // [V,D]
    const float* bias = (const float*)d_in[3];   // [V]
    float* out = (float*)d_out;                  // [B,T,U,V]

    dim3 ggrid(V / BN, M_PAD / BM);              // 8 x 32 = 256 CTAs
    joiner_gemm_kernel<<<ggrid, 256>>>(enc, pred, W);
    joiner_bcast_kernel<<<M_ENC, 256>>>(bias, out);
}

// round 8
// speedup vs baseline: 2.2621x; 1.2915x over previous
#include <cuda_runtime.h>
#include <cuda_fp16.h>
#include <mma.h>
#include <cstdint>
#include <cstddef>

using namespace nvcuda;

// Problem constants
constexpr int Bq = 8;
constexpr int T  = 200;
constexpr int U  = 50;
constexpr int D  = 512;    // K
constexpr int V  = 1024;   // N
constexpr int M_ENC  = Bq * T;          // 1600
constexpr int M_TOT  = M_ENC + Bq * U;  // 2000
constexpr int M_PAD  = 2048;

// GEMM tiling (fp16 HMMA): KC=32 halfs per stage, depth-2 cp.async
constexpr int BM  = 64;
constexpr int BN  = 128;
constexpr int KC  = 32;          // halfs per stage (2 k16 steps)
constexpr int NS  = D / KC;      // 16 stages
constexpr int LDH = KC + 8;      // 40 halfs (80 B) row stride, 16B-aligned

// Scratch
__device__ float  EP[M_PAD * V];   // [X;pad] @ W^T
__device__ __half Xh[M_PAD * D];   // fp16 [enc;pred;0]
__device__ __half Wh[V * D];       // fp16 W

__device__ __forceinline__ void cp_async16(void* smem_dst, const void* gsrc) {
    uint32_t s = (uint32_t)__cvta_generic_to_shared(smem_dst);
    asm volatile("cp.async.cg.shared.global [%0], [%1], 16;\n" :: "r"(s), "l"(gsrc));
}
__device__ __forceinline__ void cp_commit() {
    asm volatile("cp.async.commit_group;\n" ::);
}

// ---------------------------------------------------------------------------
// Kernel 0: pack [enc;pred;0] and W to fp16 (RN). Removes GEMM predication.
// ---------------------------------------------------------------------------
__global__ __launch_bounds__(256)
void pack_half_kernel(const float* __restrict__ enc,
                      const float* __restrict__ pred,
                      const float* __restrict__ W)
{
    const int idx = blockIdx.x * blockDim.x + threadIdx.x;   // float4 index
    constexpr int NX4 = M_PAD * D / 4;   // 262144
    constexpr int NW4 = V * D / 4;       // 131072
    if (idx < NX4) {
        const int row = idx >> 7;            // 128 float4 per row
        const int c   = (idx & 127) * 4;
        float4 v = make_float4(0.f, 0.f, 0.f, 0.f);
        if (row < M_ENC)
            v = *reinterpret_cast<const float4*>(enc + (size_t)row * D + c);
        else if (row < M_TOT)
            v = *reinterpret_cast<const float4*>(pred + (size_t)(row - M_ENC) * D + c);
        __half2 h0 = __floats2half2_rn(v.x, v.y);
        __half2 h1 = __floats2half2_rn(v.z, v.w);
        *reinterpret_cast<__half2*>(Xh + (size_t)idx * 4)     = h0;
        *reinterpret_cast<__half2*>(Xh + (size_t)idx * 4 + 2) = h1;
    } else if (idx < NX4 + NW4) {
        const int j = idx - NX4;
        float4 v = *reinterpret_cast<const float4*>(W + (size_t)j * 4);
        __half2 h0 = __floats2half2_rn(v.x, v.y);
        __half2 h1 = __floats2half2_rn(v.z, v.w);
        *reinterpret_cast<__half2*>(Wh + (size_t)j * 4)     = h0;
        *reinterpret_cast<__half2*>(Wh + (size_t)j * 4 + 2) = h1;
    }
}

// ---------------------------------------------------------------------------
// Kernel 1: EP = Xh @ Wh^T  (fp16 wmma m16n16k16, fp32 accum, double buffer)
//   64x128 tiles -> 256 CTAs, 2 CTAs/SM.
// ---------------------------------------------------------------------------
__global__ __launch_bounds__(256, 2)
void joiner_gemm_kernel()
{
    __shared__ __half As[2][BM * LDH];   // (m, k) row-major, lda = LDH
    __shared__ __half Bs[2][BN * LDH];   // (n, k): (k,n) at Bs[n*LDH+k] -> col_major

    const int m0 = blockIdx.y * BM;
    const int n0 = blockIdx.x * BN;
    const int tid  = threadIdx.x;        // 256
    const int warp = tid >> 5;           // 8 warps: 2(M) x 4(N)
    const int wm   = (warp >> 2) * 32;   // 0 / 32
    const int wn   = (warp & 3)  * 32;   // 0..96

    wmma::fragment<wmma::accumulator, 16, 16, 16, float> acc[2][2];
#pragma unroll
    for (int i = 0; i < 2; i++)
#pragma unroll
        for (int j = 0; j < 2; j++)
            wmma::fill_fragment(acc[i][j], 0.0f);

    auto load_stage = [&](int ks, int buf) {
        const int k0 = ks * KC;
        // A: 64 rows x 32 halfs (64B) = 256 x 16B chunks, 1/thread
        {
            const int r = tid >> 2;
            const int c = (tid & 3) * 8;          // half offset within stage row
            cp_async16(&As[buf][r * LDH + c], Xh + (size_t)(m0 + r) * D + k0 + c);
        }
        // B: 128 rows x 32 halfs = 512 chunks, 2/thread
#pragma unroll
        for (int t = 0; t < 2; t++) {
            const int idx = tid + t * 256;
            const int n   = idx >> 2;
            const int c   = (idx & 3) * 8;
            cp_async16(&Bs[buf][n * LDH + c], Wh + (size_t)(n0 + n) * D + k0 + c);
        }
        cp_commit();
    };

    load_stage(0, 0);

    for (int ks = 0; ks < NS; ks++) {
        const int buf = ks & 1;
        if (ks + 1 < NS) {
            load_stage(ks + 1, buf ^ 1);
            asm volatile("cp.async.wait_group 1;\n" ::);
        } else {
            asm volatile("cp.async.wait_group 0;\n" ::);
        }
        __syncthreads();

#pragma unroll
        for (int kk = 0; kk < KC; kk += 16) {
            wmma::fragment<wmma::matrix_a, 16, 16, 16, __half, wmma::row_major> af[2];
            wmma::fragment<wmma::matrix_b, 16, 16, 16, __half, wmma::col_major> bf[2];
#pragma unroll
            for (int i = 0; i < 2; i++)
                wmma::load_matrix_sync(af[i], &As[buf][(wm + i * 16) * LDH + kk], LDH);
#pragma unroll
            for (int j = 0; j < 2; j++)
                wmma::load_matrix_sync(bf[j], &Bs[buf][(wn + j * 16) * LDH + kk], LDH);
#pragma unroll
            for (int i = 0; i < 2; i++)
#pragma unroll
                for (int j = 0; j < 2; j++)
                    wmma::mma_sync(acc[i][j], af[i], bf[j], acc[i][j]);
        }
        __syncthreads();
    }

    // store (padded EP rows absorb the M=2000 ragged tail)
#pragma unroll
    for (int i = 0; i < 2; i++)
#pragma unroll
        for (int j = 0; j < 2; j++)
            wmma::store_matrix_sync(&EP[(size_t)(m0 + wm + i * 16) * V + (n0 + wn + j * 16)],
                                    acc[i][j], V, wmma::mem_row_major);
}

// ---------------------------------------------------------------------------
// Kernel 2: out[b,t,u,v] = EP[b*T+t, v] + EP[1600 + b*U+u, v] + bias[v]
//   Proven config: one CTA per (b,t), plain STG.128, unroll 5.
// ---------------------------------------------------------------------------
__global__ __launch_bounds__(256, 8)
void joiner_bcast_kernel(const float* __restrict__ bias,
                         float* __restrict__ out)
{
    const int bt  = blockIdx.x;          // 0..1599
    const int b   = bt / T;
    const int tid = threadIdx.x;         // 256 threads * 4 floats = V

    float4 e  = *reinterpret_cast<const float4*>(EP + (size_t)bt * V + tid * 4);
    float4 bb = *reinterpret_cast<const float4*>(bias + tid * 4);
    e.x += bb.x; e.y += bb.y; e.z += bb.z; e.w += bb.w;

    const float* Pbase = EP + (size_t)(M_ENC + b * U) * V + tid * 4;
    float*       Obase = out + (size_t)bt * U * V + tid * 4;

#pragma unroll 5
    for (int u = 0; u < U; u++) {
        float4 p = *reinterpret_cast<const float4*>(Pbase + (size_t)u * V);
        float4 o;
        o.x = e.x + p.x;
        o.y = e.y + p.y;
        o.z = e.z + p.z;
        o.w = e.w + p.w;
        *reinterpret_cast<float4*>(Obase + (size_t)u * V) = o;
    }
}

// ---------------------------------------------------------------------------
extern "C" void kernel_launch(void* const* d_in, const int* in_sizes, int n_in,
                              void* d_out, int out_size)
{
    const float* enc  = (const float*)d_in[0];   // [B,T,D]
    const float* pred = (const float*)d_in[1];   // [B,U,D]
    const float* W    = (const float*)d_in[2];   // [V,D]
    const float* bias = (const float*)d_in[3];   // [V]
    float* out = (float*)d_out;                  // [B,T,U,V]

    constexpr int NPACK = (M_PAD * D + V * D) / 4;   // 393216
    pack_half_kernel<<<NPACK / 256, 256>>>(enc, pred, W);

    dim3 ggrid(V / BN, M_PAD / BM);                  // 8 x 32 = 256 CTAs
    joiner_gemm_kernel<<<ggrid, 256>>>();

    joiner_bcast_kernel<<<M_ENC, 256>>>(bias, out);
}